// round 1
// baseline (speedup 1.0000x reference)
#include <cuda_runtime.h>
#include <cstdint>

// Problem constants
#define BATCH 32
#define SEQ   2048
#define E     1024           // ENC == DEC == 1024
#define MROWS (BATCH * SEQ)  // 65536

// Scratch (device globals: no allocation allowed)
__device__ float g_qq[BATCH * E];        // b2 + b1 + dec@w2, per (b,e)
__device__ float g_scores[BATCH * SEQ];
__device__ float g_attn[BATCH * SEQ];
__device__ float g_part[8 * BATCH * E];  // context partials over s-chunks

// ---------------------------------------------------------------------------
// helpers
// ---------------------------------------------------------------------------
__device__ __forceinline__ float to_tf32(float x) {
    uint32_t u;
    asm("cvt.rna.tf32.f32 %0, %1;" : "=r"(u) : "f"(x));
    return __uint_as_float(u);
}

__device__ __forceinline__ void mma_tf32(float c[4], const uint32_t a[4], const uint32_t b[2]) {
    asm volatile(
        "mma.sync.aligned.m16n8k8.row.col.f32.tf32.tf32.f32 "
        "{%0,%1,%2,%3}, {%4,%5,%6,%7}, {%8,%9}, {%0,%1,%2,%3};\n"
        : "+f"(c[0]), "+f"(c[1]), "+f"(c[2]), "+f"(c[3])
        : "r"(a[0]), "r"(a[1]), "r"(a[2]), "r"(a[3]),
          "r"(b[0]), "r"(b[1]));
}

// ---------------------------------------------------------------------------
// Kernel A: qq[b,e] = sum_d dec[b,d] * w2[d,e] + b2[e] + b1[e]
// grid (BATCH, 8), block 128
// ---------------------------------------------------------------------------
__global__ void qq_kernel(const float* __restrict__ dec,
                          const float* __restrict__ w2,
                          const float* __restrict__ b1,
                          const float* __restrict__ b2) {
    int b = blockIdx.x;
    int e = blockIdx.y * 128 + threadIdx.x;
    const float* drow = dec + (size_t)b * E;
    float acc = 0.f;
#pragma unroll 4
    for (int d = 0; d < E; d++) {
        acc += __ldg(drow + d) * __ldg(w2 + (size_t)d * E + e);
    }
    g_qq[b * E + e] = acc + __ldg(b1 + e) + __ldg(b2 + e);
}

// ---------------------------------------------------------------------------
// Kernel B (heavy): scores[b,s] = sum_e tanh( (enc@w1)[b,s,e] + qq[b,e] ) * v[e]
// tf32 mma.sync GEMM, fused epilogue. CTA tile M=128, loops N chunks of 128.
// ---------------------------------------------------------------------------
#define BM 128
#define BN 128
#define BK 32

__global__ __launch_bounds__(256)
void scores_kernel(const float* __restrict__ enc,
                   const float* __restrict__ w1,
                   const float* __restrict__ v) {
    __shared__ float sA[BK][BM + 4];   // transposed: [k][m], stride 132 -> conflict-free frags
    __shared__ float sB[BK][BN + 4];   // [k][n]
    __shared__ float sPart[2][BM];     // per n-warp partial scores (deterministic, no atomics)

    const int tid  = threadIdx.x;
    const int warp = tid >> 5;
    const int lane = tid & 31;
    const int wm = warp & 3;           // m warp: 0..3  (32 rows each)
    const int wn = warp >> 2;          // n warp: 0..1  (64 cols each)
    const int grp = lane >> 2;         // 0..7
    const int tig = lane & 3;          // 0..3

    const int row0 = blockIdx.x * BM;  // 512 blocks
    const int b    = row0 >> 11;       // row0 / 2048 (tiles never straddle batches)

    if (tid < 2 * BM) ((float*)sPart)[tid] = 0.f;

    for (int nc = 0; nc < E / BN; nc++) {
        const int n0 = nc * BN;
        float acc[2][8][4];
#pragma unroll
        for (int mf = 0; mf < 2; mf++)
#pragma unroll
            for (int nf = 0; nf < 8; nf++)
#pragma unroll
                for (int i = 0; i < 4; i++) acc[mf][nf][i] = 0.f;

        for (int kc = 0; kc < E; kc += BK) {
            __syncthreads();
            // --- load A tile (128 x 32) -> transposed smem, tf32-rounded ---
            {
                int r = tid >> 3;         // 0..31
                int q = tid & 7;          // float4 idx in k
#pragma unroll
                for (int i = 0; i < 4; i++) {
                    int rr = r + i * 32;
                    float4 a = *(const float4*)(enc + (size_t)(row0 + rr) * E + kc + q * 4);
                    sA[q * 4 + 0][rr] = to_tf32(a.x);
                    sA[q * 4 + 1][rr] = to_tf32(a.y);
                    sA[q * 4 + 2][rr] = to_tf32(a.z);
                    sA[q * 4 + 3][rr] = to_tf32(a.w);
                }
            }
            // --- load B tile (32 x 128) ---
            {
                int k = tid >> 5;         // 0..7
                int q = tid & 31;         // float4 idx in n
#pragma unroll
                for (int i = 0; i < 4; i++) {
                    int kk = k + i * 8;
                    float4 w = *(const float4*)(w1 + (size_t)(kc + kk) * E + n0 + q * 4);
                    sB[kk][q * 4 + 0] = to_tf32(w.x);
                    sB[kk][q * 4 + 1] = to_tf32(w.y);
                    sB[kk][q * 4 + 2] = to_tf32(w.z);
                    sB[kk][q * 4 + 3] = to_tf32(w.w);
                }
            }
            __syncthreads();

#pragma unroll
            for (int ks = 0; ks < BK / 8; ks++) {
                const int kb = ks * 8;
                uint32_t afrag[2][4];
#pragma unroll
                for (int mf = 0; mf < 2; mf++) {
                    int m = wm * 32 + mf * 16;
                    afrag[mf][0] = __float_as_uint(sA[kb + tig    ][m + grp    ]);
                    afrag[mf][1] = __float_as_uint(sA[kb + tig    ][m + grp + 8]);
                    afrag[mf][2] = __float_as_uint(sA[kb + tig + 4][m + grp    ]);
                    afrag[mf][3] = __float_as_uint(sA[kb + tig + 4][m + grp + 8]);
                }
                uint32_t bfrag[8][2];
#pragma unroll
                for (int nf = 0; nf < 8; nf++) {
                    int n = wn * 64 + nf * 8;
                    bfrag[nf][0] = __float_as_uint(sB[kb + tig    ][n + grp]);
                    bfrag[nf][1] = __float_as_uint(sB[kb + tig + 4][n + grp]);
                }
#pragma unroll
                for (int mf = 0; mf < 2; mf++)
#pragma unroll
                    for (int nf = 0; nf < 8; nf++)
                        mma_tf32(acc[mf][nf], afrag[mf], bfrag[nf]);
            }
        }

        // --- fused epilogue: + qq, tanh, * v, reduce over n within this chunk ---
        const float* qrow = g_qq + b * E;
#pragma unroll
        for (int mf = 0; mf < 2; mf++) {
            float sumA = 0.f, sumB = 0.f;
#pragma unroll
            for (int nf = 0; nf < 8; nf++) {
                int cg = n0 + wn * 64 + nf * 8 + tig * 2;
                float q0 = qrow[cg], q1 = qrow[cg + 1];
                float v0 = __ldg(v + cg), v1 = __ldg(v + cg + 1);
                sumA += tanhf(acc[mf][nf][0] + q0) * v0 + tanhf(acc[mf][nf][1] + q1) * v1;
                sumB += tanhf(acc[mf][nf][2] + q0) * v0 + tanhf(acc[mf][nf][3] + q1) * v1;
            }
            // reduce across tig (lanes differing in bits 0..1 share a row)
            sumA += __shfl_xor_sync(0xffffffffu, sumA, 1);
            sumA += __shfl_xor_sync(0xffffffffu, sumA, 2);
            sumB += __shfl_xor_sync(0xffffffffu, sumB, 1);
            sumB += __shfl_xor_sync(0xffffffffu, sumB, 2);
            if (tig == 0) {
                int r = wm * 32 + mf * 16 + grp;
                sPart[wn][r]     += sumA;   // unique writer per (wn,row): race-free
                sPart[wn][r + 8] += sumB;
            }
        }
    }
    __syncthreads();
    if (tid < BM) g_scores[row0 + tid] = sPart[0][tid] + sPart[1][tid];
}

// ---------------------------------------------------------------------------
// Softmax over s per batch. grid BATCH, block 256.
// ---------------------------------------------------------------------------
__global__ void softmax_kernel() {
    const int b = blockIdx.x;
    const int tid = threadIdx.x;
    __shared__ float red[8];

    float vals[8];
    float mx = -1e30f;
#pragma unroll
    for (int i = 0; i < 8; i++) {
        vals[i] = g_scores[b * SEQ + i * 256 + tid];
        mx = fmaxf(mx, vals[i]);
    }
#pragma unroll
    for (int o = 16; o > 0; o >>= 1) mx = fmaxf(mx, __shfl_xor_sync(0xffffffffu, mx, o));
    if ((tid & 31) == 0) red[tid >> 5] = mx;
    __syncthreads();
    mx = red[0];
#pragma unroll
    for (int w = 1; w < 8; w++) mx = fmaxf(mx, red[w]);

    float sum = 0.f;
#pragma unroll
    for (int i = 0; i < 8; i++) {
        vals[i] = __expf(vals[i] - mx) ;
        sum += vals[i];
    }
#pragma unroll
    for (int o = 16; o > 0; o >>= 1) sum += __shfl_xor_sync(0xffffffffu, sum, o);
    __syncthreads();
    if ((tid & 31) == 0) red[tid >> 5] = sum;
    __syncthreads();
    sum = 0.f;
#pragma unroll
    for (int w = 0; w < 8; w++) sum += red[w];
    float inv = 1.f / sum;
#pragma unroll
    for (int i = 0; i < 8; i++) g_attn[b * SEQ + i * 256 + tid] = vals[i] * inv;
}

// ---------------------------------------------------------------------------
// Context partials: part[sc,b,e] = sum_{s in chunk} attn[b,s]*enc[b,s,e]
// grid (BATCH, 4, 8), block 256
// ---------------------------------------------------------------------------
__global__ void ctx_partial_kernel(const float* __restrict__ enc) {
    const int b  = blockIdx.x;
    const int e  = blockIdx.y * 256 + threadIdx.x;
    const int sc = blockIdx.z;
    __shared__ float sat[256];
    const int s0 = sc * 256;
    sat[threadIdx.x] = g_attn[b * SEQ + s0 + threadIdx.x];
    __syncthreads();
    const float* p = enc + ((size_t)b * SEQ + s0) * E + e;
    float acc = 0.f;
#pragma unroll 4
    for (int s = 0; s < 256; s++) acc += sat[s] * p[(size_t)s * E];
    g_part[((size_t)sc * BATCH + b) * E + e] = acc;
}

__global__ void ctx_reduce_kernel(float* __restrict__ out) {
    int i = blockIdx.x * 256 + threadIdx.x;   // 32768 outputs
    float a = 0.f;
#pragma unroll
    for (int sc = 0; sc < 8; sc++) a += g_part[(size_t)sc * BATCH * E + i];
    out[i] = a;
}

// ---------------------------------------------------------------------------
extern "C" void kernel_launch(void* const* d_in, const int* in_sizes, int n_in,
                              void* d_out, int out_size) {
    const float* enc = (const float*)d_in[0];   // [32,2048,1024]
    const float* dec = (const float*)d_in[1];   // [32,1,1024]
    const float* w1  = (const float*)d_in[2];   // [1024,1024]
    const float* b1  = (const float*)d_in[3];   // [1024]
    const float* w2  = (const float*)d_in[4];   // [1024,1024]
    const float* b2  = (const float*)d_in[5];   // [1024]
    const float* v   = (const float*)d_in[6];   // [1024,1]
    // d_in[7] = bv: uniform shift under softmax -> no effect, skipped.
    float* out = (float*)d_out;                 // [32,1024]

    qq_kernel<<<dim3(BATCH, E / 128), 128>>>(dec, w2, b1, b2);
    scores_kernel<<<MROWS / BM, 256>>>(enc, w1, v);
    softmax_kernel<<<BATCH, 256>>>();
    ctx_partial_kernel<<<dim3(BATCH, E / 256, SEQ / 256), 256>>>(enc);
    ctx_reduce_kernel<<<BATCH * E / 256, 256>>>(out);
}

// round 3
// speedup vs baseline: 1.3356x; 1.3356x over previous
#include <cuda_runtime.h>
#include <cstdint>

// Problem constants
#define BATCH 32
#define SEQ   2048
#define E     1024
#define MROWS (BATCH * SEQ)  // 65536

// Device scratch (no allocation allowed)
__device__ float g_qq[BATCH * E];
__device__ float g_scores[BATCH * SEQ];
__device__ float g_attn[BATCH * SEQ];
__device__ float g_part[8 * BATCH * E];

// ---------------------------------------------------------------------------
// scores kernel geometry
// ---------------------------------------------------------------------------
// CTA: 128 rows (M) x full E, scalar score out per row.
// N passes: 4 chunks of BN=256. K pipeline: BK=16 per stage, 4 stages,
// one flat 256-step pipeline across all (nc, k) — prefetch runs through epilogues.
#define BM 128
#define BN 256
#define BKS 16
#define NSTAGE 4
#define NSTEPS 256                 // 4 nc * 64 k-steps

#define A_ROW_B   80               // 16 floats + 4 pad  -> conflict-free frags
#define B_ROW_B   1040             // 256 floats + 4 pad
#define A_BYTES   (BM * A_ROW_B)   // 10240
#define B_BYTES   (BKS * B_ROW_B)  // 16640
#define STAGE_BYTES (A_BYTES + B_BYTES)      // 26880
#define SM_SCORE  0                // 128 floats
#define SM_EP     512              // 4*128 floats
#define SM_STAGE  2560
#define SMEM_TOTAL (SM_STAGE + NSTAGE * STAGE_BYTES)   // 110080

// ---------------------------------------------------------------------------
// helpers
// ---------------------------------------------------------------------------
__device__ __forceinline__ uint32_t smem_u32(const void* p) {
    uint32_t a;
    asm("{ .reg .u64 t; cvta.to.shared.u64 t, %1; cvt.u32.u64 %0, t; }" : "=r"(a) : "l"(p));
    return a;
}
__device__ __forceinline__ void cp_async16(uint32_t dst, const void* src) {
    asm volatile("cp.async.cg.shared.global [%0], [%1], 16;" :: "r"(dst), "l"(src));
}
__device__ __forceinline__ void cp_commit() {
    asm volatile("cp.async.commit_group;" ::: "memory");
}
template <int N>
__device__ __forceinline__ void cp_wait() {
    asm volatile("cp.async.wait_group %0;" :: "n"(N) : "memory");
}
__device__ __forceinline__ void mma_tf32(float c[4], const uint32_t a[4], const uint32_t b[2]) {
    asm volatile(
        "mma.sync.aligned.m16n8k8.row.col.f32.tf32.tf32.f32 "
        "{%0,%1,%2,%3}, {%4,%5,%6,%7}, {%8,%9}, {%0,%1,%2,%3};\n"
        : "+f"(c[0]), "+f"(c[1]), "+f"(c[2]), "+f"(c[3])
        : "r"(a[0]), "r"(a[1]), "r"(a[2]), "r"(a[3]), "r"(b[0]), "r"(b[1]));
}

// ---------------------------------------------------------------------------
// qq[b,e] = dec[b]@w2[:,e] + b1[e] + b2[e]
// ---------------------------------------------------------------------------
__global__ void qq_kernel(const float* __restrict__ dec, const float* __restrict__ w2,
                          const float* __restrict__ b1, const float* __restrict__ b2) {
    int b = blockIdx.x;
    int e = blockIdx.y * 128 + threadIdx.x;
    const float* drow = dec + (size_t)b * E;
    float acc = 0.f;
#pragma unroll 4
    for (int d = 0; d < E; d++) acc += __ldg(drow + d) * __ldg(w2 + (size_t)d * E + e);
    g_qq[b * E + e] = acc + __ldg(b1 + e) + __ldg(b2 + e);
}

// ---------------------------------------------------------------------------
// scores kernel: pipelined tf32 mma.sync GEMM + fused tanh/v-dot epilogue
// grid 512 CTAs, 512 threads
// ---------------------------------------------------------------------------
__device__ __forceinline__ void load_stage_body(uint32_t st, const float* __restrict__ enc,
                                                const float* __restrict__ w1,
                                                int row0, int step, int tid) {
    const int kc = (step & 63) * BKS;
    const int n0 = (step >> 6) * BN;
    // A tile: 128 rows x 16 floats; 512 x 16B ops, 1 per thread
    {
        int m = tid >> 2, kq = tid & 3;
        cp_async16(st + m * A_ROW_B + kq * 16,
                   enc + (size_t)(row0 + m) * E + kc + kq * 4);
    }
    // B tile: 16 k-rows x 256 floats from w1 (k-major); 1024 x 16B ops, 2 per thread
    {
        uint32_t bb = st + A_BYTES;
#pragma unroll
        for (int j = 0; j < 2; j++) {
            int q = tid + j * 512;
            int k = q >> 6, n4 = q & 63;
            cp_async16(bb + k * B_ROW_B + n4 * 16,
                       w1 + (size_t)(kc + k) * E + n0 + n4 * 4);
        }
    }
}

__global__ __launch_bounds__(512, 1)
void scores_kernel(const float* __restrict__ enc, const float* __restrict__ w1,
                   const float* __restrict__ v) {
    extern __shared__ char smem[];
    const uint32_t sbase = smem_u32(smem);
    const int tid = threadIdx.x;
    const int warp = tid >> 5, lane = tid & 31;
    const int wm = warp & 3;          // 4 m-warps: 32 rows each
    const int wn = warp >> 2;         // 4 n-warps: 64 cols each
    const int grp = lane >> 2;        // 0..7
    const int tig = lane & 3;         // 0..3
    const int row0 = blockIdx.x * BM;
    const int b = row0 >> 11;

    float* sScore = (float*)(smem + SM_SCORE);
    float* sEp = (float*)(smem + SM_EP);
    const float* qrow = g_qq + b * E;

    if (tid < BM) sScore[tid] = 0.f;

    // preload 3 stages
#pragma unroll
    for (int s = 0; s < NSTAGE - 1; s++) {
        load_stage_body(sbase + SM_STAGE + s * STAGE_BYTES, enc, w1, row0, s, tid);
        cp_commit();
    }

    float acc[2][8][4];
#pragma unroll
    for (int mf = 0; mf < 2; mf++)
#pragma unroll
        for (int nf = 0; nf < 8; nf++)
#pragma unroll
            for (int i = 0; i < 4; i++) acc[mf][nf][i] = 0.f;

    for (int i = 0; i < NSTEPS; i++) {
        cp_wait<NSTAGE - 2>();
        __syncthreads();

        // prefetch stage i+3 (same slot as stage i-1, already consumed)
        if (i + NSTAGE - 1 < NSTEPS)
            load_stage_body(sbase + SM_STAGE + ((i + NSTAGE - 1) & (NSTAGE - 1)) * STAGE_BYTES,
                            enc, w1, row0, i + NSTAGE - 1, tid);
        cp_commit();   // keep group count uniform (empty groups at tail)

        // compute stage i
        {
            const char* st = smem + SM_STAGE + (i & (NSTAGE - 1)) * STAGE_BYTES;
            const char* stB = st + A_BYTES;
#pragma unroll
            for (int ks = 0; ks < 2; ks++) {
                const int kb = ks * 8;
                uint32_t afrag[2][4];
#pragma unroll
                for (int mf = 0; mf < 2; mf++) {
                    const char* ar = st + (wm * 32 + mf * 16 + grp) * A_ROW_B;
                    afrag[mf][0] = *(const uint32_t*)(ar + (kb + tig) * 4);
                    afrag[mf][1] = *(const uint32_t*)(ar + 8 * A_ROW_B + (kb + tig) * 4);
                    afrag[mf][2] = *(const uint32_t*)(ar + (kb + tig + 4) * 4);
                    afrag[mf][3] = *(const uint32_t*)(ar + 8 * A_ROW_B + (kb + tig + 4) * 4);
                }
                uint32_t bfrag[8][2];
#pragma unroll
                for (int nf = 0; nf < 8; nf++) {
                    const char* br = stB + (wn * 64 + nf * 8 + grp) * 4;
                    bfrag[nf][0] = *(const uint32_t*)(br + (kb + tig) * B_ROW_B);
                    bfrag[nf][1] = *(const uint32_t*)(br + (kb + tig + 4) * B_ROW_B);
                }
#pragma unroll
                for (int mf = 0; mf < 2; mf++)
#pragma unroll
                    for (int nf = 0; nf < 8; nf++)
                        mma_tf32(acc[mf][nf], afrag[mf], bfrag[nf]);
            }
        }

        // epilogue at end of each N pass
        if ((i & 63) == 63) {
            const int n0 = (i >> 6) * BN;
#pragma unroll
            for (int mf = 0; mf < 2; mf++) {
                float sumA = 0.f, sumB = 0.f;
#pragma unroll
                for (int nf = 0; nf < 8; nf++) {
                    int c = n0 + wn * 64 + nf * 8 + tig * 2;
                    float q0 = __ldg(qrow + c), q1 = __ldg(qrow + c + 1);
                    float v0 = __ldg(v + c), v1 = __ldg(v + c + 1);
                    sumA += tanhf(acc[mf][nf][0] + q0) * v0 + tanhf(acc[mf][nf][1] + q1) * v1;
                    sumB += tanhf(acc[mf][nf][2] + q0) * v0 + tanhf(acc[mf][nf][3] + q1) * v1;
                }
                sumA += __shfl_xor_sync(0xffffffffu, sumA, 1);
                sumA += __shfl_xor_sync(0xffffffffu, sumA, 2);
                sumB += __shfl_xor_sync(0xffffffffu, sumB, 1);
                sumB += __shfl_xor_sync(0xffffffffu, sumB, 2);
                if (tig == 0) {
                    int r = wm * 32 + mf * 16 + grp;
                    sEp[wn * BM + r] = sumA;
                    sEp[wn * BM + r + 8] = sumB;
                }
            }
            __syncthreads();
            if (tid < BM)
                sScore[tid] += sEp[tid] + sEp[BM + tid] + sEp[2 * BM + tid] + sEp[3 * BM + tid];
            // reset acc for next pass
#pragma unroll
            for (int mf = 0; mf < 2; mf++)
#pragma unroll
                for (int nf = 0; nf < 8; nf++)
#pragma unroll
                    for (int k2 = 0; k2 < 4; k2++) acc[mf][nf][k2] = 0.f;
        }
    }

    __syncthreads();
    if (tid < BM) g_scores[row0 + tid] = sScore[tid];
}

// ---------------------------------------------------------------------------
// Softmax over s per batch
// ---------------------------------------------------------------------------
__global__ void softmax_kernel() {
    const int b = blockIdx.x;
    const int tid = threadIdx.x;
    __shared__ float red[8];

    float vals[8];
    float mx = -1e30f;
#pragma unroll
    for (int i = 0; i < 8; i++) {
        vals[i] = g_scores[b * SEQ + i * 256 + tid];
        mx = fmaxf(mx, vals[i]);
    }
#pragma unroll
    for (int o = 16; o > 0; o >>= 1) mx = fmaxf(mx, __shfl_xor_sync(0xffffffffu, mx, o));
    if ((tid & 31) == 0) red[tid >> 5] = mx;
    __syncthreads();
    mx = red[0];
#pragma unroll
    for (int w = 1; w < 8; w++) mx = fmaxf(mx, red[w]);

    float sum = 0.f;
#pragma unroll
    for (int i = 0; i < 8; i++) {
        vals[i] = __expf(vals[i] - mx);
        sum += vals[i];
    }
#pragma unroll
    for (int o = 16; o > 0; o >>= 1) sum += __shfl_xor_sync(0xffffffffu, sum, o);
    __syncthreads();
    if ((tid & 31) == 0) red[tid >> 5] = sum;
    __syncthreads();
    sum = 0.f;
#pragma unroll
    for (int w = 0; w < 8; w++) sum += red[w];
    float inv = 1.f / sum;
#pragma unroll
    for (int i = 0; i < 8; i++) g_attn[b * SEQ + i * 256 + tid] = vals[i] * inv;
}

// ---------------------------------------------------------------------------
// Context
// ---------------------------------------------------------------------------
__global__ void ctx_partial_kernel(const float* __restrict__ enc) {
    const int b = blockIdx.x;
    const int e = blockIdx.y * 256 + threadIdx.x;
    const int sc = blockIdx.z;
    __shared__ float sat[256];
    const int s0 = sc * 256;
    sat[threadIdx.x] = g_attn[b * SEQ + s0 + threadIdx.x];
    __syncthreads();
    const float* p = enc + ((size_t)b * SEQ + s0) * E + e;
    float acc = 0.f;
#pragma unroll 4
    for (int s = 0; s < 256; s++) acc += sat[s] * p[(size_t)s * E];
    g_part[((size_t)sc * BATCH + b) * E + e] = acc;
}

__global__ void ctx_reduce_kernel(float* __restrict__ out) {
    int i = blockIdx.x * 256 + threadIdx.x;
    float a = 0.f;
#pragma unroll
    for (int sc = 0; sc < 8; sc++) a += g_part[(size_t)sc * BATCH * E + i];
    out[i] = a;
}

// ---------------------------------------------------------------------------
extern "C" void kernel_launch(void* const* d_in, const int* in_sizes, int n_in,
                              void* d_out, int out_size) {
    const float* enc = (const float*)d_in[0];
    const float* dec = (const float*)d_in[1];
    const float* w1  = (const float*)d_in[2];
    const float* b1  = (const float*)d_in[3];
    const float* w2  = (const float*)d_in[4];
    const float* b2  = (const float*)d_in[5];
    const float* v   = (const float*)d_in[6];
    // d_in[7] = bv: uniform shift under softmax -> no effect
    float* out = (float*)d_out;

    cudaFuncSetAttribute(scores_kernel, cudaFuncAttributeMaxDynamicSharedMemorySize, SMEM_TOTAL);

    qq_kernel<<<dim3(BATCH, E / 128), 128>>>(dec, w2, b1, b2);
    scores_kernel<<<MROWS / BM, 512, SMEM_TOTAL>>>(enc, w1, v);
    softmax_kernel<<<BATCH, 256>>>();
    ctx_partial_kernel<<<dim3(BATCH, E / 256, SEQ / 256), 256>>>(enc);
    ctx_reduce_kernel<<<BATCH * E / 256, 256>>>(out);
}

// round 7
// speedup vs baseline: 2.5474x; 1.9074x over previous
#include <cuda_runtime.h>
#include <cuda_fp16.h>
#include <cstdint>

// Problem constants
#define BATCH 32
#define SEQ   2048
#define E     1024
#define MROWS (BATCH * SEQ)  // 65536

// Device scratch (static: no allocation allowed)
__device__ __half g_enc_h[(size_t)MROWS * E];   // fp16 copy of encoder_outputs (128 MB)
__device__ __half g_w1t_h[(size_t)E * E];       // w1 transposed, fp16: w1t[e][d]
__device__ float  g_qq[BATCH * E];
__device__ float  g_scores[BATCH * SEQ];
__device__ float  g_attn[BATCH * SEQ];
__device__ float  g_part[8 * BATCH * E];

// ---------------------------------------------------------------------------
// scores geometry: CTA = 128 rows x full E. 4 N-passes of BN=256.
// K stage = 32 halves (64B rows). 4-stage cp.async pipeline, 128 flat steps.
// ---------------------------------------------------------------------------
#define BM 128
#define BN 256
#define BK 32
#define NSTAGE 4
#define NSTEPS 128                    // 4 nc * 32 k-steps

#define A_BYTES (BM * 64)             // 8192
#define B_BYTES (BN * 64)             // 16384
#define STAGE_BYTES (A_BYTES + B_BYTES)  // 24576
#define SM_SCORE 0
#define SM_EP    512
#define SM_STAGE 2560
#define SMEM_TOTAL (SM_STAGE + NSTAGE * STAGE_BYTES)   // 100864

// ---------------------------------------------------------------------------
// helpers
// ---------------------------------------------------------------------------
__device__ __forceinline__ uint32_t smem_u32(const void* p) {
    uint32_t a;
    asm("{ .reg .u64 t; cvta.to.shared.u64 t, %1; cvt.u32.u64 %0, t; }" : "=r"(a) : "l"(p));
    return a;
}
__device__ __forceinline__ void cp_async16(uint32_t dst, const void* src) {
    asm volatile("cp.async.cg.shared.global [%0], [%1], 16;" :: "r"(dst), "l"(src));
}
__device__ __forceinline__ void cp_commit() {
    asm volatile("cp.async.commit_group;" ::: "memory");
}
template <int N>
__device__ __forceinline__ void cp_wait() {
    asm volatile("cp.async.wait_group %0;" :: "n"(N) : "memory");
}
__device__ __forceinline__ void ldsm_x4(uint32_t d[4], uint32_t addr) {
    asm volatile("ldmatrix.sync.aligned.m8n8.x4.shared.b16 {%0,%1,%2,%3}, [%4];"
                 : "=r"(d[0]), "=r"(d[1]), "=r"(d[2]), "=r"(d[3]) : "r"(addr));
}
__device__ __forceinline__ void mma_f16(float c[4], const uint32_t a[4],
                                        uint32_t b0, uint32_t b1) {
    asm volatile(
        "mma.sync.aligned.m16n8k16.row.col.f32.f16.f16.f32 "
        "{%0,%1,%2,%3}, {%4,%5,%6,%7}, {%8,%9}, {%0,%1,%2,%3};\n"
        : "+f"(c[0]), "+f"(c[1]), "+f"(c[2]), "+f"(c[3])
        : "r"(a[0]), "r"(a[1]), "r"(a[2]), "r"(a[3]), "r"(b0), "r"(b1));
}

// ---------------------------------------------------------------------------
// conversion kernels (also steer ncu capture slot: scores lands at launch #3)
// ---------------------------------------------------------------------------
__global__ void conv_enc_kernel(const float* __restrict__ enc) {
    size_t i = ((size_t)blockIdx.x * 256 + threadIdx.x) * 8;
    float4 f0 = *(const float4*)(enc + i);
    float4 f1 = *(const float4*)(enc + i + 4);
    __half2 h[4];
    h[0] = __floats2half2_rn(f0.x, f0.y);
    h[1] = __floats2half2_rn(f0.z, f0.w);
    h[2] = __floats2half2_rn(f1.x, f1.y);
    h[3] = __floats2half2_rn(f1.z, f1.w);
    *(uint4*)(g_enc_h + i) = *(uint4*)h;
}

__global__ void conv_w1t_kernel(const float* __restrict__ w1) {
    __shared__ float t[32][33];
    int bx = blockIdx.x * 32, by = blockIdx.y * 32;
    int x = threadIdx.x, y0 = threadIdx.y;
#pragma unroll
    for (int j = 0; j < 32; j += 8)
        t[y0 + j][x] = w1[(size_t)(by + y0 + j) * E + bx + x];
    __syncthreads();
#pragma unroll
    for (int j = 0; j < 32; j += 8)
        g_w1t_h[(size_t)(bx + y0 + j) * E + by + x] = __float2half_rn(t[x][y0 + j]);
}

// ---------------------------------------------------------------------------
// qq[b,e] = dec[b]@w2[:,e] + b1[e] + b2[e]   (fp32, small)
// ---------------------------------------------------------------------------
__global__ void qq_kernel(const float* __restrict__ dec, const float* __restrict__ w2,
                          const float* __restrict__ b1, const float* __restrict__ b2) {
    int b = blockIdx.x;
    int e = blockIdx.y * 128 + threadIdx.x;
    const float* drow = dec + (size_t)b * E;
    float acc = 0.f;
#pragma unroll 4
    for (int d = 0; d < E; d++) acc += __ldg(drow + d) * __ldg(w2 + (size_t)d * E + e);
    g_qq[b * E + e] = acc + __ldg(b1 + e) + __ldg(b2 + e);
}

// ---------------------------------------------------------------------------
// scores kernel: fp16 mma.sync m16n8k16 + ldmatrix, fused tanh/v-dot epilogue
// grid 512 CTAs, 512 threads
// ---------------------------------------------------------------------------
__device__ __forceinline__ void load_stage_body(uint32_t st, int row0, int step, int tid) {
    const int kc = (step & 31) * BK;
    const int n0 = (step >> 5) * BN;
    // A: 128 m-rows x 64B, chunk swizzle c ^= (m>>1)&3
    {
        int m = tid >> 2, c = tid & 3;
        uint32_t dst = st + m * 64 + ((c ^ ((m >> 1) & 3)) << 4);
        cp_async16(dst, g_enc_h + (size_t)(row0 + m) * E + kc + c * 8);
    }
    // B: 256 n-rows x 64B from w1t (n-major, k contiguous)
    {
        uint32_t bb = st + A_BYTES;
#pragma unroll
        for (int j = 0; j < 2; j++) {
            int q = tid + j * 512;
            int n = q >> 2, c = q & 3;
            uint32_t dst = bb + n * 64 + ((c ^ ((n >> 1) & 3)) << 4);
            cp_async16(dst, g_w1t_h + (size_t)(n0 + n) * E + kc + c * 8);
        }
    }
}

__global__ __launch_bounds__(512, 1)
void scores_kernel(const float* __restrict__ v) {
    extern __shared__ char smem[];
    const uint32_t sbase = smem_u32(smem);
    const int tid = threadIdx.x;
    const int warp = tid >> 5, lane = tid & 31;
    const int wm = warp & 3;          // 4 m-warps: 32 rows each
    const int wn = warp >> 2;         // 4 n-warps: 64 cols each
    const int grp = lane >> 2;        // 0..7
    const int tig = lane & 3;         // 0..3
    const int row0 = blockIdx.x * BM;
    const int b = row0 >> 11;

    // ldmatrix per-lane geometry
    const int quad = lane >> 3, rin = lane & 7;
    const int qlow = quad & 1, qhi = quad >> 1;
    const int a_m = wm * 32 + qlow * 8 + rin;
    const int sw_a = (a_m >> 1) & 3;
    const uint32_t a_off = a_m * 64;
    const int b_n = wn * 64 + qlow * 8 + rin;
    const int sw_b = (b_n >> 1) & 3;
    const uint32_t b_off = b_n * 64;

    float* sScore = (float*)(smem + SM_SCORE);
    float* sEp = (float*)(smem + SM_EP);
    const float* qrow = g_qq + b * E;

    if (tid < BM) sScore[tid] = 0.f;

#pragma unroll
    for (int s = 0; s < NSTAGE - 1; s++) {
        load_stage_body(sbase + SM_STAGE + s * STAGE_BYTES, row0, s, tid);
        cp_commit();
    }

    float acc[2][8][4];
#pragma unroll
    for (int mf = 0; mf < 2; mf++)
#pragma unroll
        for (int nf = 0; nf < 8; nf++)
#pragma unroll
            for (int i = 0; i < 4; i++) acc[mf][nf][i] = 0.f;

    for (int i = 0; i < NSTEPS; i++) {
        cp_wait<NSTAGE - 2>();
        __syncthreads();

        if (i + NSTAGE - 1 < NSTEPS)
            load_stage_body(sbase + SM_STAGE + ((i + NSTAGE - 1) & (NSTAGE - 1)) * STAGE_BYTES,
                            row0, i + NSTAGE - 1, tid);
        cp_commit();  // uniform group count (empty groups at tail)

        {
            const uint32_t stA = sbase + SM_STAGE + (i & (NSTAGE - 1)) * STAGE_BYTES;
            const uint32_t stB = stA + A_BYTES;
#pragma unroll
            for (int ks = 0; ks < 2; ks++) {
                const int ch = 2 * ks + qhi;
                uint32_t af[2][4];
#pragma unroll
                for (int mf = 0; mf < 2; mf++)
                    ldsm_x4(af[mf], stA + a_off + mf * 1024 + ((ch ^ sw_a) << 4));
                uint32_t bf[4][4];
#pragma unroll
                for (int nfp = 0; nfp < 4; nfp++)
                    ldsm_x4(bf[nfp], stB + b_off + nfp * 1024 + ((ch ^ sw_b) << 4));
#pragma unroll
                for (int mf = 0; mf < 2; mf++)
#pragma unroll
                    for (int nfp = 0; nfp < 4; nfp++) {
                        mma_f16(acc[mf][2 * nfp],     af[mf], bf[nfp][0], bf[nfp][2]);
                        mma_f16(acc[mf][2 * nfp + 1], af[mf], bf[nfp][1], bf[nfp][3]);
                    }
            }
        }

        // epilogue at end of each N pass (every 32 steps)
        if ((i & 31) == 31) {
            const int n0 = (i >> 5) * BN;
#pragma unroll
            for (int mf = 0; mf < 2; mf++) {
                float sumA = 0.f, sumB = 0.f;
#pragma unroll
                for (int nf = 0; nf < 8; nf++) {
                    int c = n0 + wn * 64 + nf * 8 + tig * 2;
                    float q0 = __ldg(qrow + c), q1 = __ldg(qrow + c + 1);
                    float v0 = __ldg(v + c), v1 = __ldg(v + c + 1);
                    sumA += tanhf(acc[mf][nf][0] + q0) * v0 + tanhf(acc[mf][nf][1] + q1) * v1;
                    sumB += tanhf(acc[mf][nf][2] + q0) * v0 + tanhf(acc[mf][nf][3] + q1) * v1;
                }
                sumA += __shfl_xor_sync(0xffffffffu, sumA, 1);
                sumA += __shfl_xor_sync(0xffffffffu, sumA, 2);
                sumB += __shfl_xor_sync(0xffffffffu, sumB, 1);
                sumB += __shfl_xor_sync(0xffffffffu, sumB, 2);
                if (tig == 0) {
                    int r = wm * 32 + mf * 16 + grp;
                    sEp[wn * BM + r] = sumA;
                    sEp[wn * BM + r + 8] = sumB;
                }
            }
            __syncthreads();
            if (tid < BM)
                sScore[tid] += sEp[tid] + sEp[BM + tid] + sEp[2 * BM + tid] + sEp[3 * BM + tid];
#pragma unroll
            for (int mf = 0; mf < 2; mf++)
#pragma unroll
                for (int nf = 0; nf < 8; nf++)
#pragma unroll
                    for (int k2 = 0; k2 < 4; k2++) acc[mf][nf][k2] = 0.f;
        }
    }

    __syncthreads();
    if (tid < BM) g_scores[row0 + tid] = sScore[tid];
}

// ---------------------------------------------------------------------------
// Softmax over s per batch
// ---------------------------------------------------------------------------
__global__ void softmax_kernel() {
    const int b = blockIdx.x;
    const int tid = threadIdx.x;
    __shared__ float red[8];

    float vals[8];
    float mx = -1e30f;
#pragma unroll
    for (int i = 0; i < 8; i++) {
        vals[i] = g_scores[b * SEQ + i * 256 + tid];
        mx = fmaxf(mx, vals[i]);
    }
#pragma unroll
    for (int o = 16; o > 0; o >>= 1) mx = fmaxf(mx, __shfl_xor_sync(0xffffffffu, mx, o));
    if ((tid & 31) == 0) red[tid >> 5] = mx;
    __syncthreads();
    mx = red[0];
#pragma unroll
    for (int w = 1; w < 8; w++) mx = fmaxf(mx, red[w]);

    float sum = 0.f;
#pragma unroll
    for (int i = 0; i < 8; i++) {
        vals[i] = __expf(vals[i] - mx);
        sum += vals[i];
    }
#pragma unroll
    for (int o = 16; o > 0; o >>= 1) sum += __shfl_xor_sync(0xffffffffu, sum, o);
    __syncthreads();
    if ((tid & 31) == 0) red[tid >> 5] = sum;
    __syncthreads();
    sum = 0.f;
#pragma unroll
    for (int w = 0; w < 8; w++) sum += red[w];
    float inv = 1.f / sum;
#pragma unroll
    for (int i = 0; i < 8; i++) g_attn[b * SEQ + i * 256 + tid] = vals[i] * inv;
}

// ---------------------------------------------------------------------------
// Context
// ---------------------------------------------------------------------------
__global__ void ctx_partial_kernel(const float* __restrict__ enc) {
    const int b = blockIdx.x;
    const int e = blockIdx.y * 256 + threadIdx.x;
    const int sc = blockIdx.z;
    __shared__ float sat[256];
    const int s0 = sc * 256;
    sat[threadIdx.x] = g_attn[b * SEQ + s0 + threadIdx.x];
    __syncthreads();
    const float* p = enc + ((size_t)b * SEQ + s0) * E + e;
    float acc = 0.f;
#pragma unroll 4
    for (int s = 0; s < 256; s++) acc += sat[s] * p[(size_t)s * E];
    g_part[((size_t)sc * BATCH + b) * E + e] = acc;
}

__global__ void ctx_reduce_kernel(float* __restrict__ out) {
    int i = blockIdx.x * 256 + threadIdx.x;
    float a = 0.f;
#pragma unroll
    for (int sc = 0; sc < 8; sc++) a += g_part[(size_t)sc * BATCH * E + i];
    out[i] = a;
}

// ---------------------------------------------------------------------------
extern "C" void kernel_launch(void* const* d_in, const int* in_sizes, int n_in,
                              void* d_out, int out_size) {
    const float* enc = (const float*)d_in[0];
    const float* dec = (const float*)d_in[1];
    const float* w1  = (const float*)d_in[2];
    const float* b1  = (const float*)d_in[3];
    const float* w2  = (const float*)d_in[4];
    const float* b2  = (const float*)d_in[5];
    const float* v   = (const float*)d_in[6];
    // d_in[7] = bv: uniform shift under softmax -> no effect
    float* out = (float*)d_out;

    cudaFuncSetAttribute(scores_kernel, cudaFuncAttributeMaxDynamicSharedMemorySize, SMEM_TOTAL);

    conv_enc_kernel<<<MROWS * E / (256 * 8), 256>>>(enc);        // launch 0
    conv_w1t_kernel<<<dim3(32, 32), dim3(32, 8)>>>(w1);          // launch 1
    qq_kernel<<<dim3(BATCH, E / 128), 128>>>(dec, w2, b1, b2);   // launch 2
    scores_kernel<<<MROWS / BM, 512, SMEM_TOTAL>>>(v);           // launch 3 (ncu slot)
    softmax_kernel<<<BATCH, 256>>>();
    ctx_partial_kernel<<<dim3(BATCH, E / 256, SEQ / 256), 256>>>(enc);
    ctx_reduce_kernel<<<BATCH * E / 256, 256>>>(out);
}

// round 8
// speedup vs baseline: 2.7587x; 1.0829x over previous
#include <cuda_runtime.h>
#include <cuda_fp16.h>
#include <cstdint>

// Problem constants
#define BATCH 32
#define SEQ   2048
#define E     1024
#define MROWS (BATCH * SEQ)  // 65536

// Device scratch (static: no allocation allowed)
__device__ __half g_enc_h[(size_t)MROWS * E];   // fp16 copy of encoder_outputs (128 MB)
__device__ __half g_w1t_h[(size_t)E * E];       // w1 transposed, fp16: w1t[e][d]
__device__ float  g_qq[BATCH * E];
__device__ float  g_scores[BATCH * SEQ];
__device__ float  g_attn[BATCH * SEQ];
__device__ float  g_part[8 * BATCH * E];

// ---------------------------------------------------------------------------
// scores geometry: CTA = 128 rows x full E. 4 N-passes of BN=256.
// K stage = 64 halves (128B rows). 4-stage cp.async pipeline, 64 flat steps.
// ---------------------------------------------------------------------------
#define BM 128
#define BN 256
#define BK 64
#define NSTAGE 4
#define NSTEPS 64                     // 4 passes * 16 k-steps

#define A_BYTES (BM * 128)            // 16384
#define B_BYTES (BN * 128)            // 32768
#define STAGE_BYTES (A_BYTES + B_BYTES)  // 49152
#define SM_SCORE 0
#define SM_EP    512
#define SM_STAGE 2560
#define SMEM_TOTAL (SM_STAGE + NSTAGE * STAGE_BYTES)   // 199168

// ---------------------------------------------------------------------------
// helpers
// ---------------------------------------------------------------------------
__device__ __forceinline__ uint32_t smem_u32(const void* p) {
    uint32_t a;
    asm("{ .reg .u64 t; cvta.to.shared.u64 t, %1; cvt.u32.u64 %0, t; }" : "=r"(a) : "l"(p));
    return a;
}
__device__ __forceinline__ void cp_async16(uint32_t dst, const void* src) {
    asm volatile("cp.async.cg.shared.global [%0], [%1], 16;" :: "r"(dst), "l"(src));
}
__device__ __forceinline__ void cp_commit() {
    asm volatile("cp.async.commit_group;" ::: "memory");
}
template <int N>
__device__ __forceinline__ void cp_wait() {
    asm volatile("cp.async.wait_group %0;" :: "n"(N) : "memory");
}
__device__ __forceinline__ void ldsm_x4(uint32_t d[4], uint32_t addr) {
    asm volatile("ldmatrix.sync.aligned.m8n8.x4.shared.b16 {%0,%1,%2,%3}, [%4];"
                 : "=r"(d[0]), "=r"(d[1]), "=r"(d[2]), "=r"(d[3]) : "r"(addr));
}
__device__ __forceinline__ void mma_f16(float c[4], const uint32_t a[4],
                                        uint32_t b0, uint32_t b1) {
    asm volatile(
        "mma.sync.aligned.m16n8k16.row.col.f32.f16.f16.f32 "
        "{%0,%1,%2,%3}, {%4,%5,%6,%7}, {%8,%9}, {%0,%1,%2,%3};\n"
        : "+f"(c[0]), "+f"(c[1]), "+f"(c[2]), "+f"(c[3])
        : "r"(a[0]), "r"(a[1]), "r"(a[2]), "r"(a[3]), "r"(b0), "r"(b1));
}

// ---------------------------------------------------------------------------
// conversion kernels
// ---------------------------------------------------------------------------
__global__ void conv_enc_kernel(const float* __restrict__ enc) {
    size_t i = ((size_t)blockIdx.x * 256 + threadIdx.x) * 8;
    float4 f0 = *(const float4*)(enc + i);
    float4 f1 = *(const float4*)(enc + i + 4);
    __half2 h[4];
    h[0] = __floats2half2_rn(f0.x, f0.y);
    h[1] = __floats2half2_rn(f0.z, f0.w);
    h[2] = __floats2half2_rn(f1.x, f1.y);
    h[3] = __floats2half2_rn(f1.z, f1.w);
    *(uint4*)(g_enc_h + i) = *(uint4*)h;
}

__global__ void conv_w1t_kernel(const float* __restrict__ w1) {
    __shared__ float t[32][33];
    int bx = blockIdx.x * 32, by = blockIdx.y * 32;
    int x = threadIdx.x, y0 = threadIdx.y;
#pragma unroll
    for (int j = 0; j < 32; j += 8)
        t[y0 + j][x] = w1[(size_t)(by + y0 + j) * E + bx + x];
    __syncthreads();
#pragma unroll
    for (int j = 0; j < 32; j += 8)
        g_w1t_h[(size_t)(bx + y0 + j) * E + by + x] = __float2half_rn(t[x][y0 + j]);
}

// ---------------------------------------------------------------------------
// qq[b,e] = dec[b]@w2[:,e] + b1[e] + b2[e]   (fp32, small)
// ---------------------------------------------------------------------------
__global__ void qq_kernel(const float* __restrict__ dec, const float* __restrict__ w2,
                          const float* __restrict__ b1, const float* __restrict__ b2) {
    int b = blockIdx.x;
    int e = blockIdx.y * 128 + threadIdx.x;
    const float* drow = dec + (size_t)b * E;
    float acc = 0.f;
#pragma unroll 4
    for (int d = 0; d < E; d++) acc += __ldg(drow + d) * __ldg(w2 + (size_t)d * E + e);
    g_qq[b * E + e] = acc + __ldg(b1 + e) + __ldg(b2 + e);
}

// ---------------------------------------------------------------------------
// scores kernel: fp16 mma.sync m16n8k16 + ldmatrix, fused tanh/v-dot epilogue
// grid 512 CTAs, 512 threads
// ---------------------------------------------------------------------------
__global__ __launch_bounds__(512, 1)
void scores_kernel(const float* __restrict__ v) {
    extern __shared__ char smem[];
    const uint32_t sbase = smem_u32(smem);
    const int tid = threadIdx.x;
    const int warp = tid >> 5, lane = tid & 31;
    const int wm = warp & 3;          // 4 m-warps: 32 rows each
    const int wn = warp >> 2;         // 4 n-warps: 64 cols each
    const int grp = lane >> 2;        // 0..7
    const int tig = lane & 3;         // 0..3
    const int row0 = blockIdx.x * BM;
    const int b = row0 >> 11;

    // ldmatrix per-lane geometry (128B rows, 8x 16B chunks, swizzle c ^= row&7)
    const int quad = lane >> 3, rin = lane & 7;
    const int qlow = quad & 1, qhi = quad >> 1;
    const int a_m = wm * 32 + qlow * 8 + rin;
    const int b_n = wn * 64 + qlow * 8 + rin;
    const int sw_a = a_m & 7;
    const int sw_b = b_n & 7;

    uint32_t offKa[4], offKb[4];
#pragma unroll
    for (int ks = 0; ks < 4; ks++) {
        offKa[ks] = (uint32_t)(((2 * ks + qhi) ^ sw_a) << 4);
        offKb[ks] = (uint32_t)(((2 * ks + qhi) ^ sw_b) << 4);
    }
    const uint32_t aoff = (uint32_t)a_m * 128;
    const uint32_t boff = A_BYTES + (uint32_t)b_n * 128;

    // cp.async per-thread geometry
    const __half* srcA[2];
    uint32_t dstA[2];
#pragma unroll
    for (int j = 0; j < 2; j++) {
        int q = tid + j * 512;
        int m = q >> 3, c = q & 7;
        srcA[j] = g_enc_h + (size_t)(row0 + m) * E + c * 8;
        dstA[j] = (uint32_t)(m * 128 + ((c ^ (m & 7)) << 4));
    }
    const __half* srcB[4];
    uint32_t dstB[4];
#pragma unroll
    for (int j = 0; j < 4; j++) {
        int q = tid + j * 512;
        int n = q >> 3, c = q & 7;
        srcB[j] = g_w1t_h + (size_t)n * E + c * 8;      // pass 0 (n0 = 0)
        dstB[j] = (uint32_t)(A_BYTES + n * 128 + ((c ^ (n & 7)) << 4));
    }

    float* sScore = (float*)(smem + SM_SCORE);
    float* sEp = (float*)(smem + SM_EP);
    const float* qrow = g_qq + b * E;

    if (tid < BM) sScore[tid] = 0.f;

    // prologue: preload steps 0..2 (all pass 0)
#pragma unroll
    for (int s = 0; s < NSTAGE - 1; s++) {
        uint32_t sb = sbase + SM_STAGE + s * STAGE_BYTES;
        uint32_t koff = s * 64;       // halves
#pragma unroll
        for (int j = 0; j < 2; j++) cp_async16(sb + dstA[j], srcA[j] + koff);
#pragma unroll
        for (int j = 0; j < 4; j++) cp_async16(sb + dstB[j], srcB[j] + koff);
        cp_commit();
    }

    float acc[2][8][4];
#pragma unroll
    for (int mf = 0; mf < 2; mf++)
#pragma unroll
        for (int nf = 0; nf < 8; nf++)
#pragma unroll
            for (int i = 0; i < 4; i++) acc[mf][nf][i] = 0.f;

#pragma unroll 1
    for (int i = 0; i < NSTEPS; i++) {
        cp_wait<NSTAGE - 2>();
        __syncthreads();

        // prefetch step i+3 into slot (i+3)&3 (consumed slot of step i-1)
        if (i < NSTEPS - (NSTAGE - 1)) {
            const int s = i + NSTAGE - 1;
            if ((s & 15) == 0) {      // next N pass: advance B bases
#pragma unroll
                for (int j = 0; j < 4; j++) srcB[j] += (size_t)BN * E;
            }
            const uint32_t sb = sbase + SM_STAGE + (s & 3) * STAGE_BYTES;
            const uint32_t koff = (s & 15) * 64;   // halves
#pragma unroll
            for (int j = 0; j < 2; j++) cp_async16(sb + dstA[j], srcA[j] + koff);
#pragma unroll
            for (int j = 0; j < 4; j++) cp_async16(sb + dstB[j], srcB[j] + koff);
        }
        cp_commit();   // uniform group count (empty groups at tail)

        // compute stage i
        {
            const uint32_t stA = sbase + SM_STAGE + (i & 3) * STAGE_BYTES + aoff;
            const uint32_t stB = sbase + SM_STAGE + (i & 3) * STAGE_BYTES + boff;
#pragma unroll
            for (int ks = 0; ks < 4; ks++) {
                uint32_t af[2][4];
#pragma unroll
                for (int mf = 0; mf < 2; mf++)
                    ldsm_x4(af[mf], stA + mf * 2048 + offKa[ks]);
                uint32_t bf[4][4];
#pragma unroll
                for (int nfp = 0; nfp < 4; nfp++)
                    ldsm_x4(bf[nfp], stB + nfp * 2048 + offKb[ks]);
#pragma unroll
                for (int mf = 0; mf < 2; mf++)
#pragma unroll
                    for (int nfp = 0; nfp < 4; nfp++) {
                        mma_f16(acc[mf][2 * nfp],     af[mf], bf[nfp][0], bf[nfp][2]);
                        mma_f16(acc[mf][2 * nfp + 1], af[mf], bf[nfp][1], bf[nfp][3]);
                    }
            }
        }

        // epilogue at end of each N pass (every 16 steps)
        if ((i & 15) == 15) {
            const int n0 = (i >> 4) * BN;
#pragma unroll
            for (int mf = 0; mf < 2; mf++) {
                float sumA = 0.f, sumB = 0.f;
#pragma unroll
                for (int nf = 0; nf < 8; nf++) {
                    int c = n0 + wn * 64 + nf * 8 + tig * 2;
                    float q0 = __ldg(qrow + c), q1 = __ldg(qrow + c + 1);
                    float v0 = __ldg(v + c), v1 = __ldg(v + c + 1);
                    sumA += tanhf(acc[mf][nf][0] + q0) * v0 + tanhf(acc[mf][nf][1] + q1) * v1;
                    sumB += tanhf(acc[mf][nf][2] + q0) * v0 + tanhf(acc[mf][nf][3] + q1) * v1;
                }
                sumA += __shfl_xor_sync(0xffffffffu, sumA, 1);
                sumA += __shfl_xor_sync(0xffffffffu, sumA, 2);
                sumB += __shfl_xor_sync(0xffffffffu, sumB, 1);
                sumB += __shfl_xor_sync(0xffffffffu, sumB, 2);
                if (tig == 0) {
                    int r = wm * 32 + mf * 16 + grp;
                    sEp[wn * BM + r] = sumA;
                    sEp[wn * BM + r + 8] = sumB;
                }
            }
            __syncthreads();
            if (tid < BM)
                sScore[tid] += sEp[tid] + sEp[BM + tid] + sEp[2 * BM + tid] + sEp[3 * BM + tid];
#pragma unroll
            for (int mf = 0; mf < 2; mf++)
#pragma unroll
                for (int nf = 0; nf < 8; nf++)
#pragma unroll
                    for (int k2 = 0; k2 < 4; k2++) acc[mf][nf][k2] = 0.f;
        }
    }

    __syncthreads();
    if (tid < BM) g_scores[row0 + tid] = sScore[tid];
}

// ---------------------------------------------------------------------------
// Softmax over s per batch
// ---------------------------------------------------------------------------
__global__ void softmax_kernel() {
    const int b = blockIdx.x;
    const int tid = threadIdx.x;
    __shared__ float red[8];

    float vals[8];
    float mx = -1e30f;
#pragma unroll
    for (int i = 0; i < 8; i++) {
        vals[i] = g_scores[b * SEQ + i * 256 + tid];
        mx = fmaxf(mx, vals[i]);
    }
#pragma unroll
    for (int o = 16; o > 0; o >>= 1) mx = fmaxf(mx, __shfl_xor_sync(0xffffffffu, mx, o));
    if ((tid & 31) == 0) red[tid >> 5] = mx;
    __syncthreads();
    mx = red[0];
#pragma unroll
    for (int w = 1; w < 8; w++) mx = fmaxf(mx, red[w]);

    float sum = 0.f;
#pragma unroll
    for (int i = 0; i < 8; i++) {
        vals[i] = __expf(vals[i] - mx);
        sum += vals[i];
    }
#pragma unroll
    for (int o = 16; o > 0; o >>= 1) sum += __shfl_xor_sync(0xffffffffu, sum, o);
    __syncthreads();
    if ((tid & 31) == 0) red[tid >> 5] = sum;
    __syncthreads();
    sum = 0.f;
#pragma unroll
    for (int w = 0; w < 8; w++) sum += red[w];
    float inv = 1.f / sum;
#pragma unroll
    for (int i = 0; i < 8; i++) g_attn[b * SEQ + i * 256 + tid] = vals[i] * inv;
}

// ---------------------------------------------------------------------------
// Context (reads fp16 enc copy: half the DRAM traffic)
// grid (32, 2, 8), block 256; each thread does one half2 (2 e-columns)
// ---------------------------------------------------------------------------
__global__ void ctx_partial_kernel() {
    const int b = blockIdx.x;
    const int e2 = blockIdx.y * 256 + threadIdx.x;   // half2 index, 0..511
    const int sc = blockIdx.z;
    __shared__ float sat[256];
    const int s0 = sc * 256;
    sat[threadIdx.x] = g_attn[b * SEQ + s0 + threadIdx.x];
    __syncthreads();
    const __half2* p = (const __half2*)(g_enc_h + ((size_t)b * SEQ + s0) * E) + e2;
    float ax = 0.f, ay = 0.f;
#pragma unroll 4
    for (int s = 0; s < 256; s++) {
        float2 f = __half22float2(p[(size_t)s * (E / 2)]);
        float a = sat[s];
        ax += a * f.x;
        ay += a * f.y;
    }
    float* dst = g_part + ((size_t)sc * BATCH + b) * E + 2 * e2;
    dst[0] = ax;
    dst[1] = ay;
}

__global__ void ctx_reduce_kernel(float* __restrict__ out) {
    int i = blockIdx.x * 256 + threadIdx.x;
    float a = 0.f;
#pragma unroll
    for (int sc = 0; sc < 8; sc++) a += g_part[(size_t)sc * BATCH * E + i];
    out[i] = a;
}

// ---------------------------------------------------------------------------
extern "C" void kernel_launch(void* const* d_in, const int* in_sizes, int n_in,
                              void* d_out, int out_size) {
    const float* enc = (const float*)d_in[0];
    const float* dec = (const float*)d_in[1];
    const float* w1  = (const float*)d_in[2];
    const float* b1  = (const float*)d_in[3];
    const float* w2  = (const float*)d_in[4];
    const float* b2  = (const float*)d_in[5];
    const float* v   = (const float*)d_in[6];
    // d_in[7] = bv: uniform shift under softmax -> no effect
    float* out = (float*)d_out;

    cudaFuncSetAttribute(scores_kernel, cudaFuncAttributeMaxDynamicSharedMemorySize, SMEM_TOTAL);

    conv_enc_kernel<<<MROWS * E / (256 * 8), 256>>>(enc);        // launch 0
    conv_w1t_kernel<<<dim3(32, 32), dim3(32, 8)>>>(w1);          // launch 1
    qq_kernel<<<dim3(BATCH, E / 128), 128>>>(dec, w2, b1, b2);   // launch 2
    scores_kernel<<<MROWS / BM, 512, SMEM_TOTAL>>>(v);           // launch 3 (ncu slot)
    softmax_kernel<<<BATCH, 256>>>();
    ctx_partial_kernel<<<dim3(BATCH, 2, SEQ / 256), 256>>>();
    ctx_reduce_kernel<<<BATCH * E / 256, 256>>>(out);
}